// round 3
// baseline (speedup 1.0000x reference)
#include <cuda_runtime.h>
#include <cstdint>

// GRU B=64,T=4096,F=100,H=200,O=1. 32 clusters x 4 CTAs. Each CTA: 150 gate-cols,
// weights register-resident (160 regs/thread, packed f32x2 FMAs), h/x vector in SMEM
// broadcast-read, h exchanged via DSMEM, one cluster.sync per step.

#define Tq      4096
#define Fq      100
#define Hq      200
#define G3      600
#define CLUSTER 4
#define BG      2
#define JPC     50
#define NTHR    320
#define KPAD    320      // 100 x | 4 pad | 200 h | 16 pad
#define KHALF   160
#define HOFF    104      // h[j] lives at s_in[.][.][104+j]

struct __align__(16) Smem {
    float s_in[2][BG][KPAD];     // parity, batch: x|h vector          (5120 B)
    float gx[BG][160];           // x-part dots (from kc0)
    float gh0[BG][160];          // h-part dots from kc0
    float gh1[BG][160];          // h-part dots from kc1
    float bi_s[160];
    float bhn_s[64];
    float wo_s[64];
    float ypar[2][CLUSTER][BG];
    float ywarp[4];
};

__device__ __forceinline__ uint32_t smem_u32(const void* p) {
    return (uint32_t)__cvta_generic_to_shared(p);
}
__device__ __forceinline__ void st_cluster_f32(uint32_t laddr, uint32_t rr, float v) {
    uint32_t ra;
    asm volatile("mapa.shared::cluster.u32 %0, %1, %2;" : "=r"(ra) : "r"(laddr), "r"(rr));
    asm volatile("st.shared::cluster.f32 [%0], %1;" :: "r"(ra), "f"(v) : "memory");
}
__device__ __forceinline__ void ffma2(unsigned long long& acc,
                                      unsigned long long a, unsigned long long b) {
    asm("fma.rn.f32x2 %0, %1, %2, %0;" : "+l"(acc) : "l"(a), "l"(b));
}
__device__ __forceinline__ float fold2(unsigned long long a, unsigned long long b) {
    unsigned long long s;
    asm("add.rn.f32x2 %0, %1, %2;" : "=l"(s) : "l"(a), "l"(b));
    return __uint_as_float((unsigned)s) + __uint_as_float((unsigned)(s >> 32));
}
__device__ __forceinline__ unsigned long long pack2(float a, float b) {
    return (unsigned long long)__float_as_uint(a) |
           ((unsigned long long)__float_as_uint(b) << 32);
}
__device__ __forceinline__ float sigf(float x) {
    return __fdividef(1.0f, 1.0f + __expf(-x));
}
__device__ __forceinline__ float tanh_fast(float x) {
    return 2.0f * sigf(2.0f * x) - 1.0f;
}

__global__ void __launch_bounds__(NTHR, 1)
gru_kernel(const float* __restrict__ x,  const float* __restrict__ Wi,
           const float* __restrict__ bi, const float* __restrict__ Wh,
           const float* __restrict__ bhn, const float* __restrict__ Wo,
           const float* __restrict__ bo, float* __restrict__ out)
{
    extern __shared__ char smraw[];
    Smem* sm = reinterpret_cast<Smem*>(smraw);
    const int tid = threadIdx.x;
    uint32_t rank;
    asm("mov.u32 %0, %%cluster_ctarank;" : "=r"(rank));
    const int b0g = (blockIdx.x >> 2) * BG;

    const int wid  = tid >> 5, lane = tid & 31;
    const int kc   = (wid >= 5);                 // K-half: warps 0-4 -> kc0, 5-9 -> kc1
    const int col  = (kc ? wid - 5 : wid) * 32 + lane;   // 0..159 (150 real)

    // ---- register-resident weights: this thread's column, K-half slice ----
    ulonglong2 wreg[40];
    {
        int gcol = 0;
        const bool real = (col < 150);
        if (real) {
            int g = col / JPC, jj = col - g * JPC;
            gcol = g * Hq + (int)rank * JPC + jj;
        }
        #pragma unroll
        for (int q = 0; q < 40; ++q) {
            float v[4];
            #pragma unroll
            for (int r = 0; r < 4; ++r) {
                int e = kc * KHALF + q * 4 + r;
                float val = 0.f;
                if (real) {
                    if (e < Fq)                 val = Wi[(size_t)e * G3 + gcol];
                    else if (e >= HOFF && e < HOFF + Hq)
                                                val = Wh[(size_t)(e - HOFF) * G3 + gcol];
                }
                v[r] = val;
            }
            wreg[q].x = pack2(v[0], v[1]);
            wreg[q].y = pack2(v[2], v[3]);
        }
    }

    // ---- one-time SMEM init ----
    for (int i = tid; i < 2 * BG * KPAD; i += NTHR)
        (&sm->s_in[0][0][0])[i] = 0.f;
    for (int i = tid; i < 160; i += NTHR) {
        float v = 0.f;
        if (i < 150) { int g = i / JPC, jj = i - g * JPC; v = bi[g * Hq + (int)rank * JPC + jj]; }
        sm->bi_s[i] = v;
    }
    if (tid < JPC) {
        sm->bhn_s[tid] = bhn[(int)rank * JPC + tid];
        sm->wo_s[tid]  = Wo[(int)rank * JPC + tid];
    }
    __syncthreads();
    // stage x for t=0
    if (tid < 200) {
        int b = tid >= 100, f = tid - b * 100;
        sm->s_in[0][b][f] = x[(size_t)(b0g + b) * (Tq * Fq) + f];
    }
    const float bo0 = bo[0];

    __syncthreads();
    asm volatile("barrier.cluster.arrive.aligned;" ::: "memory");
    asm volatile("barrier.cluster.wait.aligned;"   ::: "memory");

    const int eb = tid >> 6, jj = tid & 63;      // epilogue map (tid<128, jj<50)
    const int jg = (int)rank * JPC + jj;

    int par = 0;
    for (int t = 0; t < Tq; ++t) {
        const int nxt = par ^ 1;

        // prefetch x_{t+1}
        float xr = 0.f;
        const bool hasx = (t + 1 < Tq) && (tid < 200);
        int pb = tid >= 100, pf = tid - pb * 100;
        if (hasx) xr = x[(size_t)(b0g + pb) * (Tq * Fq) + (size_t)(t + 1) * Fq + pf];

        // ---- dot phase: warp-uniform v loads (broadcast), packed FMAs ----
        const ulonglong2* vp0 = reinterpret_cast<const ulonglong2*>(&sm->s_in[par][0][kc * KHALF]);
        const ulonglong2* vp1 = reinterpret_cast<const ulonglong2*>(&sm->s_in[par][1][kc * KHALF]);
        unsigned long long axA0 = 0, axA1 = 0, ahA0 = 0, ahA1 = 0;
        unsigned long long axB0 = 0, axB1 = 0, ahB0 = 0, ahB1 = 0;
        if (kc == 0) {
            #pragma unroll
            for (int q = 0; q < 26; ++q) {       // elements 0..103: x (+pad)
                ulonglong2 a = vp0[q], b = vp1[q];
                ffma2(axA0, wreg[q].x, a.x); ffma2(axB0, wreg[q].x, b.x);
                ffma2(axA1, wreg[q].y, a.y); ffma2(axB1, wreg[q].y, b.y);
            }
            #pragma unroll
            for (int q = 26; q < 40; ++q) {      // elements 104..159: h[0..55]
                ulonglong2 a = vp0[q], b = vp1[q];
                ffma2(ahA0, wreg[q].x, a.x); ffma2(ahB0, wreg[q].x, b.x);
                ffma2(ahA1, wreg[q].y, a.y); ffma2(ahB1, wreg[q].y, b.y);
            }
        } else {
            #pragma unroll
            for (int q = 0; q < 40; ++q) {       // elements 160..319: h[56..199] (+pad)
                ulonglong2 a = vp0[q], b = vp1[q];
                ffma2(ahA0, wreg[q].x, a.x); ffma2(ahB0, wreg[q].x, b.x);
                ffma2(ahA1, wreg[q].y, a.y); ffma2(ahB1, wreg[q].y, b.y);
            }
        }
        if (kc == 0) {
            sm->gx [0][col] = fold2(axA0, axA1);
            sm->gx [1][col] = fold2(axB0, axB1);
            sm->gh0[0][col] = fold2(ahA0, ahA1);
            sm->gh0[1][col] = fold2(ahB0, ahB1);
        } else {
            sm->gh1[0][col] = fold2(ahA0, ahA1);
            sm->gh1[1][col] = fold2(ahB0, ahB1);
        }
        __syncthreads();

        // ---- epilogue: gates, h update, DSMEM exchange, y partial ----
        float ycon = 0.f;
        if (tid < 128 && jj < JPC) {
            int cr = jj, cz = 50 + jj, cn = 100 + jj;
            float ar  = sm->gx[eb][cr] + sm->gh0[eb][cr] + sm->gh1[eb][cr] + sm->bi_s[jj];
            float az  = sm->gx[eb][cz] + sm->gh0[eb][cz] + sm->gh1[eb][cz] + sm->bi_s[50 + jj];
            float gxn = sm->gx[eb][cn] + sm->bi_s[100 + jj];
            float ghn = sm->gh0[eb][cn] + sm->gh1[eb][cn] + sm->bhn_s[jj];
            float r = sigf(ar), z = sigf(az);
            float n = tanh_fast(gxn + r * ghn);
            float hold = sm->s_in[par][eb][HOFF + jg];
            float hnew = n + z * (hold - n);
            uint32_t la = smem_u32(&sm->s_in[nxt][eb][HOFF + jg]);
            #pragma unroll
            for (uint32_t rr = 0; rr < CLUSTER; ++rr) st_cluster_f32(la, rr, hnew);
            ycon = hnew * sm->wo_s[jj];
        }
        if (tid < 128) {
            #pragma unroll
            for (int m = 16; m > 0; m >>= 1) ycon += __shfl_xor_sync(0xffffffffu, ycon, m);
            if (lane == 0) sm->ywarp[wid] = ycon;
        }
        if (hasx) sm->s_in[nxt][pb][pf] = xr;
        __syncthreads();

        if (tid < BG) {
            float yl = sm->ywarp[2 * tid] + sm->ywarp[2 * tid + 1];
            uint32_t la = smem_u32(&sm->ypar[t & 1][rank][tid]);
            st_cluster_f32(la, 0u, yl);
        }
        asm volatile("barrier.cluster.arrive.aligned;" ::: "memory");
        asm volatile("barrier.cluster.wait.aligned;"   ::: "memory");

        if (rank == 0 && tid < BG) {
            const float* yp = &sm->ypar[t & 1][0][0];
            float y = (yp[0 * BG + tid] + yp[1 * BG + tid])
                    + (yp[2 * BG + tid] + yp[3 * BG + tid]) + bo0;
            out[(size_t)(b0g + tid) * Tq + t] = y;
        }
        par = nxt;
    }
}

extern "C" void kernel_launch(void* const* d_in, const int* in_sizes, int n_in,
                              void* d_out, int out_size) {
    (void)in_sizes; (void)n_in; (void)out_size;
    const float* x   = (const float*)d_in[0];
    const float* Wi  = (const float*)d_in[1];
    const float* bi  = (const float*)d_in[2];
    const float* Wh  = (const float*)d_in[3];
    const float* bhn = (const float*)d_in[4];
    const float* Wo  = (const float*)d_in[5];
    const float* bo  = (const float*)d_in[6];
    float* out = (float*)d_out;

    cudaFuncSetAttribute(gru_kernel, cudaFuncAttributeMaxDynamicSharedMemorySize,
                         (int)sizeof(Smem));

    cudaLaunchConfig_t cfg = {};
    cfg.gridDim  = dim3(128, 1, 1);
    cfg.blockDim = dim3(NTHR, 1, 1);
    cfg.dynamicSmemBytes = sizeof(Smem);
    cfg.stream = 0;
    cudaLaunchAttribute attr[1];
    attr[0].id = cudaLaunchAttributeClusterDimension;
    attr[0].val.clusterDim.x = CLUSTER;
    attr[0].val.clusterDim.y = 1;
    attr[0].val.clusterDim.z = 1;
    cfg.attrs = attr;
    cfg.numAttrs = 1;

    cudaLaunchKernelEx(&cfg, gru_kernel, x, Wi, bi, Wh, bhn, Wo, bo, out);
}

// round 5
// speedup vs baseline: 1.7210x; 1.7210x over previous
#include <cuda_runtime.h>
#include <cstdint>

// GRU B=64,T=4096,F=100,H=200,O=1. One persistent cluster kernel (32 clusters x 4 CTAs).
// Phase A: each CTA computes its private gx slice (x·Wi for its 150 gate-cols, 2 batches,
//          all t) into __device__ scratch, CTA-private layout [blk][t][b][160].
// Phase B: recurrence; Wh register-resident (52 packed regs/thread, K-half split),
//          h in SMEM broadcast-read, h exchanged via DSMEM, one cluster.sync per step.

#define Tq      4096
#define Fq      100
#define Hq      200
#define G3      600
#define CLUSTER 4
#define BG      2
#define JPC     50
#define NTHR    320
#define KHH     104              // K-half for h (200 -> 2x104, pad zero)
#define TT      32               // phase-A tile rows
#define GRID    128

__device__ float g_gx[(size_t)GRID * Tq * BG * 160];   // 671 MB CTA-private scratch

__device__ __forceinline__ uint32_t smem_u32(const void* p) {
    return (uint32_t)__cvta_generic_to_shared(p);
}
__device__ __forceinline__ void st_cluster_f32(uint32_t laddr, uint32_t rr, float v) {
    uint32_t ra;
    asm volatile("mapa.shared::cluster.u32 %0, %1, %2;" : "=r"(ra) : "r"(laddr), "r"(rr));
    asm volatile("st.shared::cluster.f32 [%0], %1;" :: "r"(ra), "f"(v) : "memory");
}
__device__ __forceinline__ void ffma2(unsigned long long& acc,
                                      unsigned long long a, unsigned long long b) {
    asm("fma.rn.f32x2 %0, %1, %2, %0;" : "+l"(acc) : "l"(a), "l"(b));
}
__device__ __forceinline__ float fold2(unsigned long long a, unsigned long long b) {
    unsigned long long s;
    asm("add.rn.f32x2 %0, %1, %2;" : "=l"(s) : "l"(a), "l"(b));
    return __uint_as_float((unsigned)s) + __uint_as_float((unsigned)(s >> 32));
}
__device__ __forceinline__ unsigned long long pack2(float a, float b) {
    return (unsigned long long)__float_as_uint(a) |
           ((unsigned long long)__float_as_uint(b) << 32);
}
__device__ __forceinline__ float sigf(float x) {
    return __fdividef(1.0f, 1.0f + __expf(-x));
}
__device__ __forceinline__ float tanh_fast(float x) {
    return 2.0f * sigf(2.0f * x) - 1.0f;
}

struct __align__(16) Smem {
    float h[2][BG][208];        // parity, batch: h (padded 200->208, pads zeroed)
    float gh[2][BG][160];       // K-half partial dots [kh][b][col]
    float bi_s[160];
    float bhn_s[64];
    float wo_s[64];
    float ypar[2][CLUSTER][BG];
    float ywarp[4];
    float xs[BG][TT][104];      // phase-A x staging (pads 100..103 zeroed)
};

__global__ void __launch_bounds__(NTHR, 1)
gru_kernel(const float* __restrict__ x,  const float* __restrict__ Wi,
           const float* __restrict__ bi, const float* __restrict__ Wh,
           const float* __restrict__ bhn, const float* __restrict__ Wo,
           const float* __restrict__ bo, float* __restrict__ out)
{
    extern __shared__ char smraw[];
    Smem* sm = reinterpret_cast<Smem*>(smraw);
    const int tid = threadIdx.x;
    uint32_t rank;
    asm("mov.u32 %0, %%cluster_ctarank;" : "=r"(rank));
    const int b0g = (blockIdx.x >> 2) * BG;
    float* gsl = &g_gx[(size_t)blockIdx.x * Tq * (BG * 160)];

    // ---- one-time SMEM init ----
    for (int i = tid; i < 2 * BG * 208; i += NTHR)
        (&sm->h[0][0][0])[i] = 0.f;
    for (int i = tid; i < 160; i += NTHR) {
        float v = 0.f;
        if (i < 150) { int g = i / JPC, jj = i - g * JPC; v = bi[g * Hq + (int)rank * JPC + jj]; }
        sm->bi_s[i] = v;
    }
    if (tid < JPC) {
        sm->bhn_s[tid] = bhn[(int)rank * JPC + tid];
        sm->wo_s[tid]  = Wo[(int)rank * JPC + tid];
    }
    // zero xs pad columns 100..103 (persist across tiles)
    for (int i = tid; i < BG * TT * 4; i += NTHR) {
        int b2 = i / (TT * 4), rem = i - b2 * (TT * 4);
        sm->xs[b2][rem >> 2][100 + (rem & 3)] = 0.f;
    }
    const float bo0 = bo[0];

    // ================= Phase A: gx = x · Wi for my slice =================
    {
        const int c   = tid >> 1;        // 0..159 (c<150 real)
        const int b   = tid & 1;
        const bool act = (c < 150);
        int gcol = 0;
        if (act) { int g = c / JPC, j2 = c - g * JPC; gcol = g * Hq + (int)rank * JPC + j2; }

        // Wi column -> 26 packed regs covering k = 0..103 (100 real + 4 zero pad)
        ulonglong2 wr[26];
        #pragma unroll
        for (int q = 0; q < 26; ++q) {
            float v[4];
            #pragma unroll
            for (int r = 0; r < 4; ++r) {
                int k = q * 4 + r;
                v[r] = (act && k < Fq) ? Wi[(size_t)k * G3 + gcol] : 0.f;
            }
            wr[q].x = pack2(v[0], v[1]);
            wr[q].y = pack2(v[2], v[3]);
        }

        for (int t0 = 0; t0 < Tq; t0 += TT) {
            __syncthreads();
            for (int i = tid; i < BG * TT * Fq; i += NTHR) {
                int b2 = i / (TT * Fq), rem = i - b2 * (TT * Fq);
                int r = rem / Fq, f = rem - r * Fq;
                sm->xs[b2][r][f] =
                    x[(size_t)(b0g + b2) * (Tq * Fq) + (size_t)(t0 + r) * Fq + f];
            }
            __syncthreads();
            if (act) {
                for (int r = 0; r < TT; ++r) {
                    const ulonglong2* vp = reinterpret_cast<const ulonglong2*>(sm->xs[b][r]);
                    unsigned long long a0 = 0, a1 = 0;
                    #pragma unroll
                    for (int q = 0; q < 26; ++q) {
                        ulonglong2 v = vp[q];
                        ffma2(a0, wr[q].x, v.x);
                        ffma2(a1, wr[q].y, v.y);
                    }
                    gsl[(size_t)(t0 + r) * (BG * 160) + b * 160 + c] = fold2(a0, a1);
                }
            }
        }
    }
    __syncthreads();   // gx writes visible CTA-wide (block-scope fence)

    // ================= Phase B: recurrence =================
    const int wid  = tid >> 5, lane = tid & 31;
    const int kh   = (wid >= 5);                         // K-half
    const int col  = (kh ? wid - 5 : wid) * 32 + lane;   // 0..159 (150 real)

    // register-resident Wh: column col, K-half slice (104 floats = 52 regs)
    ulonglong2 wreg[26];
    {
        int gcol = 0;
        const bool real = (col < 150);
        if (real) {
            int g = col / JPC, jj = col - g * JPC;
            gcol = g * Hq + (int)rank * JPC + jj;
        }
        #pragma unroll
        for (int q = 0; q < 26; ++q) {
            float v[4];
            #pragma unroll
            for (int r = 0; r < 4; ++r) {
                int k = kh * KHH + q * 4 + r;
                v[r] = (real && k < Hq) ? Wh[(size_t)k * G3 + gcol] : 0.f;
            }
            wreg[q].x = pack2(v[0], v[1]);
            wreg[q].y = pack2(v[2], v[3]);
        }
    }

    __syncthreads();
    asm volatile("barrier.cluster.arrive.aligned;" ::: "memory");
    asm volatile("barrier.cluster.wait.aligned;"   ::: "memory");

    const int eb = tid >> 6, jj = tid & 63;      // epilogue map (tid<128, jj<50)
    const bool epi = (tid < 128) && (jj < JPC);
    const int jg = (int)rank * JPC + jj;
    const size_t gxo = epi ? ((size_t)eb * 160 + jj) : 0;

    // preload gx(t=0)
    float gr = 0.f, gz = 0.f, gn = 0.f;
    if (epi) {
        gr = gsl[gxo + 0];
        gz = gsl[gxo + 50];
        gn = gsl[gxo + 100];
    }

    int par = 0;
    for (int t = 0; t < Tq; ++t) {
        const int nxt = par ^ 1;

        // prefetch gx(t+1) (hidden under the dot phase)
        float nr = 0.f, nz = 0.f, nn = 0.f;
        if (epi && (t + 1 < Tq)) {
            const float* p = gsl + (size_t)(t + 1) * (BG * 160) + gxo;
            nr = p[0]; nz = p[50]; nn = p[100];
        }

        // ---- dot phase: h-part, warp-uniform v broadcasts, packed FMA2 ----
        {
            const ulonglong2* vp0 = reinterpret_cast<const ulonglong2*>(&sm->h[par][0][kh * KHH]);
            const ulonglong2* vp1 = reinterpret_cast<const ulonglong2*>(&sm->h[par][1][kh * KHH]);
            unsigned long long a0x = 0, a0y = 0, a1x = 0, a1y = 0;
            #pragma unroll
            for (int q = 0; q < 26; ++q) {
                ulonglong2 v0 = vp0[q], v1 = vp1[q];
                ffma2(a0x, wreg[q].x, v0.x); ffma2(a0y, wreg[q].y, v0.y);
                ffma2(a1x, wreg[q].x, v1.x); ffma2(a1y, wreg[q].y, v1.y);
            }
            sm->gh[kh][0][col] = fold2(a0x, a0y);
            sm->gh[kh][1][col] = fold2(a1x, a1y);
        }
        __syncthreads();

        // ---- epilogue: gates, h update, DSMEM exchange, y partial ----
        float ycon = 0.f;
        if (epi) {
            int cr = jj, cz = JPC + jj, cn = 2 * JPC + jj;
            float ar  = gr + sm->gh[0][eb][cr] + sm->gh[1][eb][cr] + sm->bi_s[cr];
            float az  = gz + sm->gh[0][eb][cz] + sm->gh[1][eb][cz] + sm->bi_s[cz];
            float ghn = sm->gh[0][eb][cn] + sm->gh[1][eb][cn] + sm->bhn_s[jj];
            float r = sigf(ar), z = sigf(az);
            float n = tanh_fast(gn + sm->bi_s[cn] + r * ghn);
            float hold = sm->h[par][eb][jg];
            float hnew = n + z * (hold - n);
            uint32_t la = smem_u32(&sm->h[nxt][eb][jg]);
            #pragma unroll
            for (uint32_t rr = 0; rr < CLUSTER; ++rr) st_cluster_f32(la, rr, hnew);
            ycon = hnew * sm->wo_s[jj];
        }
        if (tid < 128) {
            #pragma unroll
            for (int m = 16; m > 0; m >>= 1) ycon += __shfl_xor_sync(0xffffffffu, ycon, m);
            if (lane == 0) sm->ywarp[wid] = ycon;
        }
        __syncthreads();

        if (tid < BG) {
            float yl = sm->ywarp[2 * tid] + sm->ywarp[2 * tid + 1];
            uint32_t la = smem_u32(&sm->ypar[t & 1][rank][tid]);
            st_cluster_f32(la, 0u, yl);
        }
        asm volatile("barrier.cluster.arrive.aligned;" ::: "memory");
        asm volatile("barrier.cluster.wait.aligned;"   ::: "memory");

        if (rank == 0 && tid < BG) {
            const float* yp = &sm->ypar[t & 1][0][0];
            float y = (yp[0 * BG + tid] + yp[1 * BG + tid])
                    + (yp[2 * BG + tid] + yp[3 * BG + tid]) + bo0;
            out[(size_t)(b0g + tid) * Tq + t] = y;
        }
        gr = nr; gz = nz; gn = nn;
        par = nxt;
    }
}

extern "C" void kernel_launch(void* const* d_in, const int* in_sizes, int n_in,
                              void* d_out, int out_size) {
    (void)in_sizes; (void)n_in; (void)out_size;
    const float* x   = (const float*)d_in[0];
    const float* Wi  = (const float*)d_in[1];
    const float* bi  = (const float*)d_in[2];
    const float* Wh  = (const float*)d_in[3];
    const float* bhn = (const float*)d_in[4];
    const float* Wo  = (const float*)d_in[5];
    const float* bo  = (const float*)d_in[6];
    float* out = (float*)d_out;

    cudaFuncSetAttribute(gru_kernel, cudaFuncAttributeMaxDynamicSharedMemorySize,
                         (int)sizeof(Smem));
    cudaLaunchConfig_t cfg = {};
    cfg.gridDim  = dim3(GRID, 1, 1);
    cfg.blockDim = dim3(NTHR, 1, 1);
    cfg.dynamicSmemBytes = sizeof(Smem);
    cfg.stream = 0;
    cudaLaunchAttribute attr[1];
    attr[0].id = cudaLaunchAttributeClusterDimension;
    attr[0].val.clusterDim.x = CLUSTER;
    attr[0].val.clusterDim.y = 1;
    attr[0].val.clusterDim.z = 1;
    cfg.attrs = attr;
    cfg.numAttrs = 1;
    cudaLaunchKernelEx(&cfg, gru_kernel, x, Wi, bi, Wh, bhn, Wo, bo, out);
}